// round 15
// baseline (speedup 1.0000x reference)
#include <cuda_runtime.h>
#include <cuda_bf16.h>
#include <cuda_fp16.h>
#include <cstdint>

// Problem constants
#define NPIX   65536      // B*H*W = 4*128*128
#define CCH    128        // channels
#define NQKV   324        // 81 * 4 heads
#define HW     16384      // H*W per image
#define NV     1152       // 9 * 128
#define SPITCH 136        // smem row pitch (halves)
#define APITCH 328        // att smem row pitch (halves)
#define TILE_H   (128 * SPITCH)          // halves per 128-row tile
#define TILE64_H (64 * SPITCH)           // halves per 64-row tile

#define ATT_SMEM  (4 * TILE_H * 2 + 128 * APITCH * 2)        // MF=4 kernel
#define G64_SMEM  ((2 * TILE64_H + 2 * TILE_H) * 2)          // A64(h,l)+B128(h,l)

// ---------------------------------------------------------------------------
// Scratch (device globals)
// ---------------------------------------------------------------------------
__device__ __nv_bfloat16 g_xh[(size_t)NPIX * CCH];
__device__ __nv_bfloat16 g_xl[(size_t)NPIX * CCH];
__device__ __nv_bfloat16 g_wqkv_h[NQKV * CCH];
__device__ __nv_bfloat16 g_wqkv_l[NQKV * CCH];
__device__ __nv_bfloat16 g_wv_h[NV * CCH];
__device__ __nv_bfloat16 g_wv_l[NV * CCH];
__device__ __nv_bfloat16 g_wpr_h[CCH * CCH];
__device__ __nv_bfloat16 g_wpr_l[CCH * CCH];
__device__ __half g_attp[(size_t)NPIX * NQKV];   // softmax probs (fp16)
__device__ __half g_u16[(size_t)9 * NPIX * CCH]; // U planes [q][g][c]
__device__ __half g_out16[(size_t)NPIX * NV];    // combine out [g][p][c]

// ---------------------------------------------------------------------------
__device__ __forceinline__ void split_bf16(float v, __nv_bfloat16& h, __nv_bfloat16& l) {
    h = __float2bfloat16_rn(v);
    l = __float2bfloat16_rn(v - __bfloat162float(h));
}

__global__ void conv_x_kernel(const float* __restrict__ x) {
    int idx = blockIdx.x * blockDim.x + threadIdx.x;   // over NPIX*64
    if (idx >= NPIX * 64) return;
    float2 f = ((const float2*)x)[idx];
    __nv_bfloat16 hx, lx, hy, ly;
    split_bf16(f.x, hx, lx);
    split_bf16(f.y, hy, ly);
    ((__nv_bfloat162*)g_xh)[idx] = __nv_bfloat162(hx, hy);
    ((__nv_bfloat162*)g_xl)[idx] = __nv_bfloat162(lx, ly);
}

__global__ void conv_w_kernel(const float* __restrict__ wqkv,
                              const float* __restrict__ wv,
                              const float* __restrict__ wproj) {
    int t = blockIdx.x * blockDim.x + threadIdx.x;
    if (t < NQKV * CCH) split_bf16(wqkv[t], g_wqkv_h[t], g_wqkv_l[t]);
    if (t < NV * CCH)   split_bf16(wv[t],   g_wv_h[t],   g_wv_l[t]);
    if (t < CCH * CCH)  split_bf16(wproj[t], g_wpr_h[t], g_wpr_l[t]);
}

// ---------------------------------------------------------------------------
#define MMA_BF16(d, a, b0v, b1v)                                              \
    asm volatile("mma.sync.aligned.m16n8k16.row.col.f32.bf16.bf16.f32 "       \
                 "{%0,%1,%2,%3},{%4,%5,%6,%7},{%8,%9},{%0,%1,%2,%3};"         \
                 : "+f"(d[0]), "+f"(d[1]), "+f"(d[2]), "+f"(d[3])             \
                 : "r"(a[0]), "r"(a[1]), "r"(a[2]), "r"(a[3]),                \
                   "r"(b0v), "r"(b1v))

#define LDSM4(r, addr)                                                        \
    asm volatile("ldmatrix.sync.aligned.m8n8.x4.shared.b16 {%0,%1,%2,%3}, [%4];" \
                 : "=r"((r)[0]), "=r"((r)[1]), "=r"((r)[2]), "=r"((r)[3])     \
                 : "r"(addr))

__device__ __forceinline__ void cp_async16(void* sptr, const void* gptr) {
    uint32_t saddr = (uint32_t)__cvta_generic_to_shared(sptr);
    asm volatile("cp.async.cg.shared.global [%0], [%1], 16;" :: "r"(saddr), "l"(gptr));
}
#define CP_COMMIT()  asm volatile("cp.async.commit_group;")
#define CP_WAIT0()   asm volatile("cp.async.wait_group 0;")

// synchronous tile pair load (bounds-checked), ROWS rows
template <int ROWS>
__device__ __forceinline__ void load_tile(const __nv_bfloat16* __restrict__ Hg,
                                          const __nv_bfloat16* __restrict__ Lg,
                                          __nv_bfloat16* Hs, __nv_bfloat16* Ls,
                                          int base_row, int row_limit, int tid) {
#pragma unroll
    for (int it = 0; it < ROWS / 16; ++it) {
        int idx = tid + it * 256;
        int row = idx >> 4, f4 = idx & 15;
        int grow = base_row + row;
        float4 h4 = make_float4(0.f, 0.f, 0.f, 0.f), l4 = h4;
        if (grow < row_limit) {
            h4 = ((const float4*)(Hg + (size_t)grow * 128))[f4];
            l4 = ((const float4*)(Lg + (size_t)grow * 128))[f4];
        }
        *(float4*)(Hs + row * SPITCH + f4 * 8) = h4;
        *(float4*)(Ls + row * SPITCH + f4 * 8) = l4;
    }
}

// async tile pair load (no bounds), ROWS rows
template <int ROWS>
__device__ __forceinline__ void load_tile_async(const __nv_bfloat16* __restrict__ Hg,
                                                const __nv_bfloat16* __restrict__ Lg,
                                                __nv_bfloat16* Hs, __nv_bfloat16* Ls,
                                                int base_row, int tid) {
#pragma unroll
    for (int it = 0; it < ROWS / 16; ++it) {
        int idx = tid + it * 256;
        int row = idx >> 4, f4 = idx & 15;
        cp_async16(Hs + row * SPITCH + f4 * 8, Hg + (size_t)(base_row + row) * 128 + f4 * 8);
        cp_async16(Ls + row * SPITCH + f4 * 8, Lg + (size_t)(base_row + row) * 128 + f4 * 8);
    }
}

// fused fold + split loader: A-tile (64 rows) for proj, gathered from g_out16
__device__ __forceinline__ void load_fold_tile(__nv_bfloat16* Hs, __nv_bfloat16* Ls,
                                               int bm, int tid) {
#pragma unroll
    for (int it = 0; it < 16; ++it) {
        int idx = tid + it * 256;          // 0..4095
        int row = idx >> 6;                // 0..63
        int pc  = idx & 63;                // half2 pair (channels 2pc, 2pc+1)
        int g = bm + row;
        int b = g >> 14, n = g & (HW - 1);
        int i = n >> 7, j = n & 127;
        float ax = 0.f, ay = 0.f;
#pragma unroll
        for (int dr = -1; dr <= 1; ++dr) {
#pragma unroll
            for (int ds = -1; ds <= 1; ++ds) {
                int r = i + dr, s = j + ds;
                if ((unsigned)r < 128u && (unsigned)s < 128u) {
                    int gp = (b << 14) + (r << 7) + s;
                    int p2 = (1 - dr) * 3 + (1 - ds);
                    half2 h = *(const half2*)&g_out16[(size_t)gp * NV + (p2 << 7) + pc * 2];
                    float2 f = __half22float2(h);
                    ax += f.x; ay += f.y;
                }
            }
        }
        __nv_bfloat16 hx, lx, hy, ly;
        split_bf16(ax, hx, lx);
        split_bf16(ay, hy, ly);
        *(__nv_bfloat162*)(Hs + row * SPITCH + pc * 2) = __nv_bfloat162(hx, hy);
        *(__nv_bfloat162*)(Ls + row * SPITCH + pc * 2) = __nv_bfloat162(lx, ly);
    }
}

// ---------------------------------------------------------------------------
// 8-kstep MMA over resident smem tiles using ldmatrix; acc[MF][4][4]
// ---------------------------------------------------------------------------
template <int MF>
__device__ __forceinline__ void mma_compute(const __nv_bfloat16* Ah, const __nv_bfloat16* Al,
                                            const __nv_bfloat16* Bh, const __nv_bfloat16* Bl,
                                            int wm, int wn, int lane,
                                            float acc[MF][4][4]) {
#pragma unroll
    for (int a = 0; a < MF; ++a)
#pragma unroll
        for (int b = 0; b < 4; ++b)
#pragma unroll
            for (int c = 0; c < 4; ++c) acc[a][b][c] = 0.f;

    const uint32_t sAh = (uint32_t)__cvta_generic_to_shared(Ah);
    const uint32_t sAl = (uint32_t)__cvta_generic_to_shared(Al);
    const uint32_t sBh = (uint32_t)__cvta_generic_to_shared(Bh);
    const uint32_t sBl = (uint32_t)__cvta_generic_to_shared(Bl);

    const uint32_t aoff =
        (uint32_t)(((wm * (MF * 16) + (lane & 15)) * SPITCH + (lane >> 4) * 8) * 2);
    const uint32_t boff =
        (uint32_t)(((wn * 32 + ((lane >> 4) & 1) * 8 + (lane & 7)) * SPITCH +
                    ((lane >> 3) & 1) * 8) * 2);

#pragma unroll
    for (int ks = 0; ks < 8; ++ks) {
        const uint32_t kb = ks * 32;
        uint32_t ah[MF][4], al[MF][4];
#pragma unroll
        for (int mf = 0; mf < MF; ++mf) {
            const uint32_t mo = mf * (16 * SPITCH * 2);
            LDSM4(ah[mf], sAh + mo + aoff + kb);
            LDSM4(al[mf], sAl + mo + aoff + kb);
        }
        uint32_t bh[2][4], bl[2][4];
#pragma unroll
        for (int np = 0; np < 2; ++np) {
            const uint32_t no = np * (16 * SPITCH * 2);
            LDSM4(bh[np], sBh + no + boff + kb);
            LDSM4(bl[np], sBl + no + boff + kb);
        }
#pragma unroll
        for (int nf = 0; nf < 4; ++nf) {
            uint32_t bh0 = bh[nf >> 1][(nf & 1) * 2];
            uint32_t bh1 = bh[nf >> 1][(nf & 1) * 2 + 1];
            uint32_t bl0 = bl[nf >> 1][(nf & 1) * 2];
            uint32_t bl1 = bl[nf >> 1][(nf & 1) * 2 + 1];
#pragma unroll
            for (int mf = 0; mf < MF; ++mf) {
                MMA_BF16(acc[mf][nf], ah[mf], bh0, bh1);
                MMA_BF16(acc[mf][nf], ah[mf], bl0, bl1);
                MMA_BF16(acc[mf][nf], al[mf], bh0, bh1);
            }
        }
    }
}

// ---------------------------------------------------------------------------
// att GEMM (M=128, all 3 n-tiles, A resident) + in-smem softmax + prob store
// ---------------------------------------------------------------------------
__global__ void __launch_bounds__(256) att_kernel() {
    extern __shared__ __nv_bfloat16 sm[];
    __nv_bfloat16* Ah = sm;
    __nv_bfloat16* Al = sm + TILE_H;
    __nv_bfloat16* Bh = sm + 2 * TILE_H;
    __nv_bfloat16* Bl = sm + 3 * TILE_H;
    __half* att_s = (__half*)(sm + 4 * TILE_H);

    const int tid = threadIdx.x;
    const int bm = blockIdx.x * 128;
    const int wid = tid >> 5, lane = tid & 31;
    const int wm = wid >> 2, wn = wid & 3;
    const int g = lane >> 2, tg = lane & 3;

    load_tile<128>(g_xh, g_xl, Ah, Al, bm, NPIX, tid);

    for (int nt = 0; nt < 3; ++nt) {
        __syncthreads();
        load_tile<128>(g_wqkv_h, g_wqkv_l, Bh, Bl, nt * 128, NQKV, tid);
        __syncthreads();
        float acc[4][4][4];
        mma_compute<4>(Ah, Al, Bh, Bl, wm, wn, lane, acc);
#pragma unroll
        for (int mf = 0; mf < 4; ++mf) {
            int row = wm * 64 + mf * 16 + g;
#pragma unroll
            for (int nf = 0; nf < 4; ++nf) {
                int cc = nt * 128 + wn * 32 + nf * 8 + tg * 2;
                if (cc < NQKV) {
                    *(half2*)(att_s + row * APITCH + cc) =
                        __floats2half2_rn(acc[mf][nf][0], acc[mf][nf][1]);
                    *(half2*)(att_s + (row + 8) * APITCH + cc) =
                        __floats2half2_rn(acc[mf][nf][2], acc[mf][nf][3]);
                }
            }
        }
    }
    __syncthreads();

    // softmax over each 9-group, in smem
    const float scale = 0.17677669529663687f;  // 32^-0.5
    for (int t = tid; t < 128 * 36; t += 256) {
        int row = t / 36, grp = t % 36;
        __half* pp = att_s + row * APITCH + grp * 9;
        float v[9], m = -1e30f;
#pragma unroll
        for (int q = 0; q < 9; ++q) { v[q] = __half2float(pp[q]) * scale; m = fmaxf(m, v[q]); }
        float s = 0.f;
#pragma unroll
        for (int q = 0; q < 9; ++q) { v[q] = __expf(v[q] - m); s += v[q]; }
        float inv = 1.f / s;
#pragma unroll
        for (int q = 0; q < 9; ++q) pp[q] = __float2half_rn(v[q] * inv);
    }
    __syncthreads();

    // coalesced prob store
    for (int t = tid; t < 128 * NQKV; t += 256) {
        int row = t / NQKV, col = t - row * NQKV;
        g_attp[(size_t)(bm + row) * NQKV + col] = att_s[row * APITCH + col];
    }
}

// ---------------------------------------------------------------------------
// U GEMM: M=64 tiles (2 blocks/SM), A resident, loop 9 q-tiles
// ---------------------------------------------------------------------------
__global__ void __launch_bounds__(256) mma_u_kernel() {
    extern __shared__ __nv_bfloat16 sm[];
    __nv_bfloat16* Ah = sm;
    __nv_bfloat16* Al = sm + TILE64_H;
    __nv_bfloat16* Bh = sm + 2 * TILE64_H;
    __nv_bfloat16* Bl = sm + 2 * TILE64_H + TILE_H;

    const int tid = threadIdx.x;
    const int bm = blockIdx.x * 64;
    const int wid = tid >> 5, lane = tid & 31;
    const int wm = wid >> 2, wn = wid & 3;
    const int g = lane >> 2, tg = lane & 3;

    load_tile_async<64>(g_xh, g_xl, Ah, Al, bm, tid);
    CP_COMMIT();

    for (int q = 0; q < 9; ++q) {
        load_tile_async<128>(g_wv_h, g_wv_l, Bh, Bl, q * 128, tid);
        CP_COMMIT();
        CP_WAIT0();
        __syncthreads();

        float acc[2][4][4];
        mma_compute<2>(Ah, Al, Bh, Bl, wm, wn, lane, acc);

        __half* plane = g_u16 + (size_t)q * NPIX * CCH;
#pragma unroll
        for (int mf = 0; mf < 2; ++mf) {
            int row = bm + wm * 32 + mf * 16 + g;
#pragma unroll
            for (int nf = 0; nf < 4; ++nf) {
                int col = wn * 32 + nf * 8 + tg * 2;
                *(half2*)(plane + (size_t)row * 128 + col) =
                    __floats2half2_rn(acc[mf][nf][0], acc[mf][nf][1]);
                *(half2*)(plane + (size_t)(row + 8) * 128 + col) =
                    __floats2half2_rn(acc[mf][nf][2], acc[mf][nf][3]);
            }
        }
        __syncthreads();
    }
}

// ---------------------------------------------------------------------------
// projection GEMM with fused fold: A-tile = fold-gather of g_out16
// ---------------------------------------------------------------------------
__global__ void __launch_bounds__(256) mma_proj_kernel(float* __restrict__ outp) {
    extern __shared__ __nv_bfloat16 sm[];
    __nv_bfloat16* Ah = sm;
    __nv_bfloat16* Al = sm + TILE64_H;
    __nv_bfloat16* Bh = sm + 2 * TILE64_H;
    __nv_bfloat16* Bl = sm + 2 * TILE64_H + TILE_H;

    const int tid = threadIdx.x;
    const int bm = blockIdx.x * 64;
    const int wid = tid >> 5, lane = tid & 31;
    const int wm = wid >> 2, wn = wid & 3;
    const int g = lane >> 2, tg = lane & 3;

    load_fold_tile(Ah, Al, bm, tid);
    load_tile<128>(g_wpr_h, g_wpr_l, Bh, Bl, 0, CCH, tid);
    __syncthreads();
    float acc[2][4][4];
    mma_compute<2>(Ah, Al, Bh, Bl, wm, wn, lane, acc);
#pragma unroll
    for (int mf = 0; mf < 2; ++mf) {
        int row = bm + wm * 32 + mf * 16 + g;
#pragma unroll
        for (int nf = 0; nf < 4; ++nf) {
            int col = wn * 32 + nf * 8 + tg * 2;
            *(float2*)&outp[(size_t)row * 128 + col] =
                make_float2(acc[mf][nf][0], acc[mf][nf][1]);
            *(float2*)&outp[(size_t)(row + 8) * 128 + col] =
                make_float2(acc[mf][nf][2], acc[mf][nf][3]);
        }
    }
}

// ---------------------------------------------------------------------------
// combine: out[g][p][c] = sum_q att[g][h(c)][p][q] * U[g+off(q)][q][c]
// 4 pixels per block, 64 threads / pixel, half2 channels
// ---------------------------------------------------------------------------
__global__ void __launch_bounds__(256) combine_kernel() {
    const int sub = threadIdx.x >> 6;        // 0..3
    const int c2  = threadIdx.x & 63;        // half2 lane
    const int g   = blockIdx.x * 4 + sub;
    __shared__ float att_s[4][NQKV];
    const __half* ap = g_attp + (size_t)g * NQKV;
    for (int t = c2; t < 162; t += 64) {
        float2 f = __half22float2(*(const half2*)(ap + t * 2));
        att_s[sub][t * 2] = f.x;
        att_s[sub][t * 2 + 1] = f.y;
    }
    __syncthreads();

    const int b = g >> 14;
    const int n = g & (HW - 1);
    const int i = n >> 7, j = n & 127;
    float2 v[9];
#pragma unroll
    for (int q = 0; q < 9; ++q) {
        int ii = i + q / 3 - 1;
        int jj = j + q % 3 - 1;
        bool valid = ((unsigned)ii < 128u) && ((unsigned)jj < 128u);
        v[q] = valid ? __half22float2(*(const half2*)&g_u16[
                   ((size_t)q * NPIX + ((b << 14) + (ii << 7) + jj)) * 128 + c2 * 2])
                     : make_float2(0.f, 0.f);
    }
    const float* ah = att_s[sub] + (c2 >> 4) * 81;
    float2 acc[9];
#pragma unroll
    for (int p2 = 0; p2 < 9; ++p2) acc[p2] = make_float2(0.f, 0.f);
#pragma unroll
    for (int q = 0; q < 9; ++q) {
        float2 vq = v[q];
#pragma unroll
        for (int p2 = 0; p2 < 9; ++p2) {
            float w = ah[p2 * 9 + q];
            acc[p2].x += w * vq.x;
            acc[p2].y += w * vq.y;
        }
    }
    __half* op = g_out16 + (size_t)g * NV + c2 * 2;
#pragma unroll
    for (int p2 = 0; p2 < 9; ++p2)
        *(half2*)(op + (p2 << 7)) = __floats2half2_rn(acc[p2].x, acc[p2].y);
}

// ---------------------------------------------------------------------------
extern "C" void kernel_launch(void* const* d_in, const int* in_sizes, int n_in,
                              void* d_out, int out_size) {
    const float* x     = (const float*)d_in[0];
    const float* wqkv  = (const float*)d_in[1];
    const float* wv    = (const float*)d_in[2];
    const float* wproj = (const float*)d_in[3];
    float* out = (float*)d_out;

    cudaFuncSetAttribute(att_kernel,      cudaFuncAttributeMaxDynamicSharedMemorySize, ATT_SMEM);
    cudaFuncSetAttribute(mma_u_kernel,    cudaFuncAttributeMaxDynamicSharedMemorySize, G64_SMEM);
    cudaFuncSetAttribute(mma_proj_kernel, cudaFuncAttributeMaxDynamicSharedMemorySize, G64_SMEM);

    conv_x_kernel<<<(NPIX * 64 + 255) / 256, 256>>>(x);
    conv_w_kernel<<<(NV * CCH + 255) / 256, 256>>>(wqkv, wv, wproj);

    att_kernel<<<512, 256, ATT_SMEM>>>();
    mma_u_kernel<<<1024, 256, G64_SMEM>>>();
    combine_kernel<<<NPIX / 4, 256>>>();
    mma_proj_kernel<<<1024, 256, G64_SMEM>>>(out);
}